// round 7
// baseline (speedup 1.0000x reference)
#include <cuda_runtime.h>
#include <cstdint>

// Problem constants (fixed shapes from setup_inputs)
#define BB 64
#define CC 3
#define HH 224
#define WW 224
#define CW (CC * WW)          // 672
#define NN 224                // Gram size
#define TAIL 45               // 224 - int(0.8*224)
#define NSWEEP 9              // cap; early-exit may trigger sooner
#define THR 1e-12f            // relative skip threshold (cos^2)

// Scratch (device globals: allocation-free per harness rules)
__device__ float g_A[BB * HH * CW];     // masked, scaled input  [b][h][cw]
__device__ float g_G[BB * NN * NN];     // Gram A A^T per image
__device__ float g_Ut[BB * TAIL * NN];  // tail eigenvectors, row t = u_t^T
__device__ int   g_cnt[BB];             // observed-entry counts

// ---------------------------------------------------------------------------
// K1: A = (2x-1)*mask in [B,H,CW] layout; per-image mask count via atomics.
// ---------------------------------------------------------------------------
__global__ void build_kernel(const float* __restrict__ x,
                             const int* __restrict__ mask) {
    int idx = blockIdx.x * 256 + threadIdx.x;
    int b   = idx / (HH * CW);
    int rem = idx - b * (HH * CW);
    int h   = rem / CW;
    int cw  = rem - h * CW;
    int c   = cw / WW;
    int w   = cw - c * WW;

    int m = mask[idx];
    float xv = x[((b * CC + c) * HH + h) * WW + w];
    g_A[idx] = m ? (2.0f * xv - 1.0f) : 0.0f;

    int s = m;
    #pragma unroll
    for (int o = 16; o; o >>= 1) s += __shfl_xor_sync(0xffffffffu, s, o);
    __shared__ int ss[8];
    int warp = threadIdx.x >> 5, lane = threadIdx.x & 31;
    if (lane == 0) ss[warp] = s;
    __syncthreads();
    if (threadIdx.x == 0) {
        int t = 0;
        #pragma unroll
        for (int i = 0; i < 8; i++) t += ss[i];
        atomicAdd(&g_cnt[b], t);
    }
}

// ---------------------------------------------------------------------------
// K2: G = A A^T per image. grid (7,7,BB), block (16,16), 2x2 micro-tile.
// ---------------------------------------------------------------------------
__global__ void gram_kernel() {
    __shared__ float As[32][33];
    __shared__ float Bs[32][33];
    int b  = blockIdx.z;
    int i0 = blockIdx.y * 32, j0 = blockIdx.x * 32;
    const float* Ab = g_A + (size_t)b * HH * CW;
    int tx = threadIdx.x, ty = threadIdx.y;
    int t = ty * 16 + tx;

    float a00 = 0.f, a01 = 0.f, a10 = 0.f, a11 = 0.f;
    for (int k0 = 0; k0 < CW; k0 += 32) {
        #pragma unroll
        for (int q = 0; q < 4; q++) {
            int e = t + q * 256;
            int rr = e >> 5, kk = e & 31;
            As[rr][kk] = Ab[(i0 + rr) * CW + k0 + kk];
            Bs[rr][kk] = Ab[(j0 + rr) * CW + k0 + kk];
        }
        __syncthreads();
        #pragma unroll
        for (int kk = 0; kk < 32; kk++) {
            float x0 = As[2 * ty][kk], x1 = As[2 * ty + 1][kk];
            float y0 = Bs[2 * tx][kk], y1 = Bs[2 * tx + 1][kk];
            a00 += x0 * y0; a01 += x0 * y1;
            a10 += x1 * y0; a11 += x1 * y1;
        }
        __syncthreads();
    }
    float* Gb = g_G + (size_t)b * NN * NN;
    Gb[(i0 + 2 * ty    ) * NN + j0 + 2 * tx    ] = a00;
    Gb[(i0 + 2 * ty    ) * NN + j0 + 2 * tx + 1] = a01;
    Gb[(i0 + 2 * ty + 1) * NN + j0 + 2 * tx    ] = a10;
    Gb[(i0 + 2 * ty + 1) * NN + j0 + 2 * tx + 1] = a11;
}

// ---------------------------------------------------------------------------
// K3: register-resident block-tournament one-sided Jacobi.
// 224 columns = 32 blocks of 7. Per outer round: 16 warps each take one
// block-pair (14 columns, lane-sliced into 98 registers), process all 91
// column pairs register-locally (fully unrolled; skip test + norm updates
// warp-uniform), store back dirty columns. 31 rounds/sweep covers every
// block pair once => every column pair at least once per sweep.
// ---------------------------------------------------------------------------
__global__ void __launch_bounds__(512, 1) jacobi_kernel() {
    extern __shared__ float sm[];
    float* W   = sm;                    // NN*NN, column-major
    float* nrm = sm + NN * NN;          // NN squared norms (maintained)
    int*   rnk = (int*)(nrm + NN);      // NN ranks
    __shared__ int rot_flag;

    int b = blockIdx.x;
    int tid = threadIdx.x, warp = tid >> 5, lane = tid & 31;
    const float* Gb = g_G + (size_t)b * NN * NN;

    for (int i = tid; i < NN * NN; i += 512) W[i] = Gb[i];
    __syncthreads();

    // initial column squared norms: 16 warps x 14 cols
    #pragma unroll
    for (int k = 0; k < 14; k++) {
        int col = warp + 16 * k;
        const float* cc = W + col * NN;
        float s = 0.f;
        #pragma unroll
        for (int m = 0; m < 7; m++) { float v = cc[lane + 32 * m]; s += v * v; }
        #pragma unroll
        for (int o = 16; o; o >>= 1) s += __shfl_xor_sync(0xffffffffu, s, o);
        if (lane == 0) nrm[col] = s;
    }
    __syncthreads();

    for (int sw = 0; sw < NSWEEP; ++sw) {
        if (tid == 0) rot_flag = 0;
        __syncthreads();
        for (int r = 0; r < 31; ++r) {
            // block pair for this warp (tournament over 32 blocks)
            int ib, jb;
            if (warp == 0) { ib = 31; jb = r; }
            else {
                ib = r + warp; if (ib >= 31) ib -= 31;
                jb = r - warp; if (jb < 0)   jb += 31;
            }
            float* bi = W + ib * 7 * NN;
            float* bj = W + jb * 7 * NN;

            // load 14 columns into registers (lane-sliced)
            float pc[14][7];
            #pragma unroll
            for (int k = 0; k < 7; k++) {
                #pragma unroll
                for (int m = 0; m < 7; m++) {
                    pc[k][m]     = bi[k * NN + lane + 32 * m];
                    pc[7 + k][m] = bj[k * NN + lane + 32 * m];
                }
            }
            // norms of the 14 columns live in lanes 0..13
            float nq = 0.f;
            if (lane < 7)       nq = nrm[ib * 7 + lane];
            else if (lane < 14) nq = nrm[jb * 7 + lane - 7];

            unsigned dirty = 0;
            int rotated = 0;

            #pragma unroll
            for (int i = 0; i < 13; i++) {
                #pragma unroll
                for (int j = i + 1; j < 14; j++) {
                    float pp = 0.f;
                    #pragma unroll
                    for (int m = 0; m < 7; m++) pp += pc[i][m] * pc[j][m];
                    #pragma unroll
                    for (int o = 16; o; o >>= 1)
                        pp += __shfl_xor_sync(0xffffffffu, pp, o);
                    float qi = __shfl_sync(0xffffffffu, nq, i);
                    float qj = __shfl_sync(0xffffffffu, nq, j);
                    if (pp * pp > THR * qi * qj) {   // warp-uniform
                        rotated = 1;
                        dirty |= (1u << i) | (1u << j);
                        float tau = (qj - qi) / (2.0f * pp);
                        float tt = 1.0f / (fabsf(tau) + sqrtf(1.0f + tau * tau));
                        if (tau < 0.f) tt = -tt;
                        float c = rsqrtf(1.0f + tt * tt);
                        float s = c * tt;
                        #pragma unroll
                        for (int m = 0; m < 7; m++) {
                            float a = pc[i][m], d = pc[j][m];
                            pc[i][m] = c * a - s * d;
                            pc[j][m] = s * a + c * d;
                        }
                        float c2 = c * c, s2 = s * s, cs2 = 2.f * c * s;
                        float qin = c2 * qi - cs2 * pp + s2 * qj;
                        float qjn = s2 * qi + cs2 * pp + c2 * qj;
                        if (lane == i) nq = qin;
                        if (lane == j) nq = qjn;
                    }
                }
            }

            // store back dirty columns + norms
            #pragma unroll
            for (int k = 0; k < 7; k++) {
                if (dirty & (1u << k)) {
                    #pragma unroll
                    for (int m = 0; m < 7; m++)
                        bi[k * NN + lane + 32 * m] = pc[k][m];
                }
                if (dirty & (1u << (7 + k))) {
                    #pragma unroll
                    for (int m = 0; m < 7; m++)
                        bj[k * NN + lane + 32 * m] = pc[7 + k][m];
                }
            }
            if (lane < 7)       nrm[ib * 7 + lane]     = nq;
            else if (lane < 14) nrm[jb * 7 + lane - 7] = nq;
            if (rotated && lane == 0) rot_flag = 1;
            __syncthreads();   // stores visible before next round's loads
        }
        if (rot_flag == 0) break;   // fully converged sweep (uniform)
    }
    __syncthreads();

    // rank of each column (0 = smallest norm), deterministic tie-break
    if (tid < NN) {
        float mine = nrm[tid];
        int rk = 0;
        for (int j = 0; j < NN; j++) {
            float o = nrm[j];
            rk += (o < mine) || (o == mine && j < tid);
        }
        rnk[tid] = rk;
    }
    __syncthreads();

    // write normalized tail-45 eigenvectors (rows of Ut^T), coalesced
    for (int t = 0; t < NN; t++) {
        int rk = rnk[t];
        if (rk < TAIL) {
            float inv = rsqrtf(nrm[t]);   // 1/lambda
            for (int rr = tid; rr < NN; rr += 512)
                g_Ut[((size_t)b * TAIL + rk) * NN + rr] = W[t * NN + rr] * inv;
        }
    }
}

// ---------------------------------------------------------------------------
// K4: R = A - Ut (Ut^T A); epilogue: /p_obs, clip, (r+1)/2, scatter to NCHW.
// Two CTAs per image (336 columns each), T in 45 registers/thread.
// ---------------------------------------------------------------------------
__global__ void __launch_bounds__(336, 2) recon_kernel(float* __restrict__ out) {
    __shared__ __align__(16) float sU[TAIL * NN];
    int b = blockIdx.x >> 1, half = blockIdx.x & 1;
    int tid = threadIdx.x;
    int cw  = half * 336 + tid;
    const float* Ub = g_Ut + (size_t)b * TAIL * NN;
    for (int i = tid; i < TAIL * NN; i += 336) sU[i] = Ub[i];
    __syncthreads();

    const float* Ab = g_A + (size_t)b * HH * CW;
    float inv_p = (float)(HH * CW) / (float)g_cnt[b];

    float acc[TAIL];
    #pragma unroll
    for (int t = 0; t < TAIL; t++) acc[t] = 0.f;

    for (int h = 0; h < HH; h += 4) {
        float a0 = Ab[(h + 0) * CW + cw];
        float a1 = Ab[(h + 1) * CW + cw];
        float a2 = Ab[(h + 2) * CW + cw];
        float a3 = Ab[(h + 3) * CW + cw];
        #pragma unroll
        for (int t = 0; t < TAIL; t++) {
            float4 u = *(const float4*)&sU[t * NN + h];
            acc[t] += u.x * a0 + u.y * a1 + u.z * a2 + u.w * a3;
        }
    }

    int c = cw / WW, w = cw - c * WW;
    float* ob = out + (((size_t)b * CC + c) * HH) * WW + w;

    for (int h = 0; h < HH; h += 4) {
        float a0 = Ab[(h + 0) * CW + cw];
        float a1 = Ab[(h + 1) * CW + cw];
        float a2 = Ab[(h + 2) * CW + cw];
        float a3 = Ab[(h + 3) * CW + cw];
        float s0 = 0.f, s1 = 0.f, s2 = 0.f, s3 = 0.f;
        #pragma unroll
        for (int t = 0; t < TAIL; t++) {
            float4 u = *(const float4*)&sU[t * NN + h];
            float tv = acc[t];
            s0 += u.x * tv; s1 += u.y * tv; s2 += u.z * tv; s3 += u.w * tv;
        }
        float r0 = (a0 - s0) * inv_p;
        float r1 = (a1 - s1) * inv_p;
        float r2 = (a2 - s2) * inv_p;
        float r3 = (a3 - s3) * inv_p;
        r0 = fminf(1.f, fmaxf(-1.f, r0));
        r1 = fminf(1.f, fmaxf(-1.f, r1));
        r2 = fminf(1.f, fmaxf(-1.f, r2));
        r3 = fminf(1.f, fmaxf(-1.f, r3));
        ob[(h + 0) * WW] = 0.5f * r0 + 0.5f;
        ob[(h + 1) * WW] = 0.5f * r1 + 0.5f;
        ob[(h + 2) * WW] = 0.5f * r2 + 0.5f;
        ob[(h + 3) * WW] = 0.5f * r3 + 0.5f;
    }
}

// ---------------------------------------------------------------------------
extern "C" void kernel_launch(void* const* d_in, const int* in_sizes, int n_in,
                              void* d_out, int out_size) {
    const float* x    = (const float*)d_in[0];
    const int*   mask = (const int*)d_in[1];
    float*       out  = (float*)d_out;

    const int JAC_SMEM = (NN * NN + NN) * (int)sizeof(float) + NN * (int)sizeof(int);

    void* cntp = nullptr;
    cudaGetSymbolAddress(&cntp, g_cnt);
    cudaMemsetAsync(cntp, 0, BB * sizeof(int));

    cudaFuncSetAttribute(jacobi_kernel,
                         cudaFuncAttributeMaxDynamicSharedMemorySize, JAC_SMEM);

    build_kernel<<<BB * HH * CW / 256, 256>>>(x, mask);
    gram_kernel<<<dim3(7, 7, BB), dim3(16, 16)>>>();
    jacobi_kernel<<<BB, 512, JAC_SMEM>>>();
    recon_kernel<<<2 * BB, 336>>>(out);
}

// round 10
// speedup vs baseline: 1.9187x; 1.9187x over previous
#include <cuda_runtime.h>
#include <cstdint>

// Problem constants (fixed shapes from setup_inputs)
#define BB 64
#define CC 3
#define HH 224
#define WW 224
#define CW (CC * WW)          // 672
#define NN 224                // Gram size
#define TAIL 45               // 224 - int(0.8*224)
#define NSWEEP 9              // cap; early-exit may trigger sooner
#define THR 1e-12f            // relative skip threshold (cos^2)

// Scratch (device globals: allocation-free per harness rules)
__device__ float g_A[BB * HH * CW];     // masked, scaled input  [b][h][cw]
__device__ float g_G[BB * NN * NN];     // Gram A A^T per image
__device__ float g_Ut[BB * TAIL * NN];  // tail eigenvectors, row t = u_t^T
__device__ int   g_cnt[BB];             // observed-entry counts

// ---------------------------------------------------------------------------
// K1: A = (2x-1)*mask in [B,H,CW] layout; per-image mask count via atomics.
// ---------------------------------------------------------------------------
__global__ void build_kernel(const float* __restrict__ x,
                             const int* __restrict__ mask) {
    int idx = blockIdx.x * 256 + threadIdx.x;
    int b   = idx / (HH * CW);
    int rem = idx - b * (HH * CW);
    int h   = rem / CW;
    int cw  = rem - h * CW;
    int c   = cw / WW;
    int w   = cw - c * WW;

    int m = mask[idx];
    float xv = x[((b * CC + c) * HH + h) * WW + w];
    g_A[idx] = m ? (2.0f * xv - 1.0f) : 0.0f;

    int s = m;
    #pragma unroll
    for (int o = 16; o; o >>= 1) s += __shfl_xor_sync(0xffffffffu, s, o);
    __shared__ int ss[8];
    int warp = threadIdx.x >> 5, lane = threadIdx.x & 31;
    if (lane == 0) ss[warp] = s;
    __syncthreads();
    if (threadIdx.x == 0) {
        int t = 0;
        #pragma unroll
        for (int i = 0; i < 8; i++) t += ss[i];
        atomicAdd(&g_cnt[b], t);
    }
}

// ---------------------------------------------------------------------------
// K2: G = A A^T per image. grid (7,7,BB), block (16,16), 2x2 micro-tile.
// ---------------------------------------------------------------------------
__global__ void gram_kernel() {
    __shared__ float As[32][33];
    __shared__ float Bs[32][33];
    int b  = blockIdx.z;
    int i0 = blockIdx.y * 32, j0 = blockIdx.x * 32;
    const float* Ab = g_A + (size_t)b * HH * CW;
    int tx = threadIdx.x, ty = threadIdx.y;
    int t = ty * 16 + tx;

    float a00 = 0.f, a01 = 0.f, a10 = 0.f, a11 = 0.f;
    for (int k0 = 0; k0 < CW; k0 += 32) {
        #pragma unroll
        for (int q = 0; q < 4; q++) {
            int e = t + q * 256;
            int rr = e >> 5, kk = e & 31;
            As[rr][kk] = Ab[(i0 + rr) * CW + k0 + kk];
            Bs[rr][kk] = Ab[(j0 + rr) * CW + k0 + kk];
        }
        __syncthreads();
        #pragma unroll
        for (int kk = 0; kk < 32; kk++) {
            float x0 = As[2 * ty][kk], x1 = As[2 * ty + 1][kk];
            float y0 = Bs[2 * tx][kk], y1 = Bs[2 * tx + 1][kk];
            a00 += x0 * y0; a01 += x0 * y1;
            a10 += x1 * y0; a11 += x1 * y1;
        }
        __syncthreads();
    }
    float* Gb = g_G + (size_t)b * NN * NN;
    Gb[(i0 + 2 * ty    ) * NN + j0 + 2 * tx    ] = a00;
    Gb[(i0 + 2 * ty    ) * NN + j0 + 2 * tx + 1] = a01;
    Gb[(i0 + 2 * ty + 1) * NN + j0 + 2 * tx    ] = a10;
    Gb[(i0 + 2 * ty + 1) * NN + j0 + 2 * tx + 1] = a11;
}

// ---------------------------------------------------------------------------
// K3: one-sided Jacobi, 8-lane-group SIMD version.
// 896 threads = 28 warps = 112 groups of 8 lanes; group g handles pair g of
// the round (all 112 pairs concurrently). Columns accessed as 7 float4 per
// lane (conflict-free: each 8-lane phase covers one contiguous 128B chunk).
// Tournament: round r pairs (223, r) and ((r+p)%223, (r-p)%223).
// Incremental norms; skip threshold relative; early exit on clean sweep.
// Numerically identical rotation sequence to the R3 kernel.
// ---------------------------------------------------------------------------
__device__ __forceinline__ void pair_ij(int r, int p, int& i, int& j) {
    if (p == 0) { i = NN - 1; j = r; }
    else {
        i = r + p; if (i >= NN - 1) i -= (NN - 1);
        j = r - p; if (j < 0)       j += (NN - 1);
    }
}

__global__ void __launch_bounds__(896, 1) jacobi_kernel() {
    extern __shared__ float sm[];
    float* W   = sm;                    // NN*NN, column-major
    float* nrm = sm + NN * NN;          // NN squared norms (maintained)
    int*   rnk = (int*)(nrm + NN);      // NN ranks
    __shared__ int rot_flag;

    int b = blockIdx.x;
    int tid = threadIdx.x, warp = tid >> 5, lane = tid & 31;
    int gl = lane & 7;                  // lane within 8-lane group
    int p  = (warp << 2) | (lane >> 3); // pair id 0..111
    const float* Gb = g_G + (size_t)b * NN * NN;

    for (int i = tid; i < NN * NN; i += 896) W[i] = Gb[i];
    __syncthreads();

    // initial column squared norms: 8 cols per warp, full-warp reduce
    #pragma unroll
    for (int k = 0; k < 8; k++) {
        int col = warp * 8 + k;
        const float* cc = W + col * NN;
        float s = 0.f;
        #pragma unroll
        for (int m = 0; m < 7; m++) { float v = cc[lane + 32 * m]; s += v * v; }
        #pragma unroll
        for (int o = 16; o; o >>= 1) s += __shfl_xor_sync(0xffffffffu, s, o);
        if (lane == 0) nrm[col] = s;
    }
    __syncthreads();

    for (int sw = 0; sw < NSWEEP; ++sw) {
        if (tid == 0) rot_flag = 0;
        __syncthreads();
        for (int r = 0; r < NN - 1; ++r) {
            int i, j; pair_ij(r, p, i, j);
            float4* ci = (float4*)(W + i * NN);
            float4* cj = (float4*)(W + j * NN);

            // dot over the group's 28-element slices; keep col i resident
            float4 wi[7];
            float pp = 0.f;
            #pragma unroll
            for (int m = 0; m < 7; m++) {
                float4 a = ci[gl + 8 * m];
                float4 u = cj[gl + 8 * m];
                wi[m] = a;
                pp += a.x * u.x + a.y * u.y + a.z * u.z + a.w * u.w;
            }
            pp += __shfl_xor_sync(0xffffffffu, pp, 4);
            pp += __shfl_xor_sync(0xffffffffu, pp, 2);
            pp += __shfl_xor_sync(0xffffffffu, pp, 1);

            float qi = nrm[i], qj = nrm[j];
            if (pp * pp > THR * qi * qj) {     // uniform within group
                float tau = (qj - qi) / (2.0f * pp);
                float tt = 1.0f / (fabsf(tau) + sqrtf(1.0f + tau * tau));
                if (tau < 0.f) tt = -tt;
                float c = rsqrtf(1.0f + tt * tt);
                float s = c * tt;
                #pragma unroll
                for (int m = 0; m < 7; m++) {
                    float4 u = cj[gl + 8 * m];  // reload j (kept regs low)
                    float4 a = wi[m];
                    float4 ni, nj;
                    ni.x = c * a.x - s * u.x;  nj.x = s * a.x + c * u.x;
                    ni.y = c * a.y - s * u.y;  nj.y = s * a.y + c * u.y;
                    ni.z = c * a.z - s * u.z;  nj.z = s * a.z + c * u.z;
                    ni.w = c * a.w - s * u.w;  nj.w = s * a.w + c * u.w;
                    ci[gl + 8 * m] = ni;
                    cj[gl + 8 * m] = nj;
                }
                if (gl == 0) {
                    float c2 = c * c, s2 = s * s, cs2 = 2.f * c * s;
                    nrm[i] = c2 * qi - cs2 * pp + s2 * qj;
                    nrm[j] = s2 * qi + cs2 * pp + c2 * qj;
                    rot_flag = 1;
                }
            }
            __syncthreads();
        }
        int done = (rot_flag == 0);
        __syncthreads();        // all reads of flag precede next reset
        if (done) break;
    }

    // rank of each column (0 = smallest norm), deterministic tie-break
    if (tid < NN) {
        float mine = nrm[tid];
        int rk = 0;
        for (int j = 0; j < NN; j++) {
            float o = nrm[j];
            rk += (o < mine) || (o == mine && j < tid);
        }
        rnk[tid] = rk;
    }
    __syncthreads();

    // write normalized tail-45 eigenvectors (rows of Ut^T), coalesced
    for (int t = 0; t < NN; t++) {
        int rk = rnk[t];
        if (rk < TAIL) {
            float inv = rsqrtf(nrm[t]);   // 1/lambda
            for (int rr = tid; rr < NN; rr += 896)
                g_Ut[((size_t)b * TAIL + rk) * NN + rr] = W[t * NN + rr] * inv;
        }
    }
}

// ---------------------------------------------------------------------------
// K4: R = A - Ut (Ut^T A); epilogue: /p_obs, clip, (r+1)/2, scatter to NCHW.
// Two CTAs per image (336 columns each), T in 45 registers/thread.
// ---------------------------------------------------------------------------
__global__ void __launch_bounds__(336, 2) recon_kernel(float* __restrict__ out) {
    __shared__ __align__(16) float sU[TAIL * NN];
    int b = blockIdx.x >> 1, half = blockIdx.x & 1;
    int tid = threadIdx.x;
    int cw  = half * 336 + tid;
    const float* Ub = g_Ut + (size_t)b * TAIL * NN;
    for (int i = tid; i < TAIL * NN; i += 336) sU[i] = Ub[i];
    __syncthreads();

    const float* Ab = g_A + (size_t)b * HH * CW;
    float inv_p = (float)(HH * CW) / (float)g_cnt[b];

    float acc[TAIL];
    #pragma unroll
    for (int t = 0; t < TAIL; t++) acc[t] = 0.f;

    for (int h = 0; h < HH; h += 4) {
        float a0 = Ab[(h + 0) * CW + cw];
        float a1 = Ab[(h + 1) * CW + cw];
        float a2 = Ab[(h + 2) * CW + cw];
        float a3 = Ab[(h + 3) * CW + cw];
        #pragma unroll
        for (int t = 0; t < TAIL; t++) {
            float4 u = *(const float4*)&sU[t * NN + h];
            acc[t] += u.x * a0 + u.y * a1 + u.z * a2 + u.w * a3;
        }
    }

    int c = cw / WW, w = cw - c * WW;
    float* ob = out + (((size_t)b * CC + c) * HH) * WW + w;

    for (int h = 0; h < HH; h += 4) {
        float a0 = Ab[(h + 0) * CW + cw];
        float a1 = Ab[(h + 1) * CW + cw];
        float a2 = Ab[(h + 2) * CW + cw];
        float a3 = Ab[(h + 3) * CW + cw];
        float s0 = 0.f, s1 = 0.f, s2 = 0.f, s3 = 0.f;
        #pragma unroll
        for (int t = 0; t < TAIL; t++) {
            float4 u = *(const float4*)&sU[t * NN + h];
            float tv = acc[t];
            s0 += u.x * tv; s1 += u.y * tv; s2 += u.z * tv; s3 += u.w * tv;
        }
        float r0 = (a0 - s0) * inv_p;
        float r1 = (a1 - s1) * inv_p;
        float r2 = (a2 - s2) * inv_p;
        float r3 = (a3 - s3) * inv_p;
        r0 = fminf(1.f, fmaxf(-1.f, r0));
        r1 = fminf(1.f, fmaxf(-1.f, r1));
        r2 = fminf(1.f, fmaxf(-1.f, r2));
        r3 = fminf(1.f, fmaxf(-1.f, r3));
        ob[(h + 0) * WW] = 0.5f * r0 + 0.5f;
        ob[(h + 1) * WW] = 0.5f * r1 + 0.5f;
        ob[(h + 2) * WW] = 0.5f * r2 + 0.5f;
        ob[(h + 3) * WW] = 0.5f * r3 + 0.5f;
    }
}

// ---------------------------------------------------------------------------
extern "C" void kernel_launch(void* const* d_in, const int* in_sizes, int n_in,
                              void* d_out, int out_size) {
    const float* x    = (const float*)d_in[0];
    const int*   mask = (const int*)d_in[1];
    float*       out  = (float*)d_out;

    const int JAC_SMEM = (NN * NN + NN) * (int)sizeof(float) + NN * (int)sizeof(int);

    void* cntp = nullptr;
    cudaGetSymbolAddress(&cntp, g_cnt);
    cudaMemsetAsync(cntp, 0, BB * sizeof(int));

    cudaFuncSetAttribute(jacobi_kernel,
                         cudaFuncAttributeMaxDynamicSharedMemorySize, JAC_SMEM);

    build_kernel<<<BB * HH * CW / 256, 256>>>(x, mask);
    gram_kernel<<<dim3(7, 7, BB), dim3(16, 16)>>>();
    jacobi_kernel<<<BB, 896, JAC_SMEM>>>();
    recon_kernel<<<2 * BB, 336>>>(out);
}

// round 12
// speedup vs baseline: 2.1856x; 1.1391x over previous
#include <cuda_runtime.h>
#include <cstdint>

// Problem constants (fixed shapes from setup_inputs)
#define BB 64
#define CC 3
#define HH 224
#define WW 224
#define CW (CC * WW)          // 672
#define NN 224                // Gram size
#define TAIL 45               // 224 - int(0.8*224)
#define NSWEEP 8              // cap; early-exit may trigger sooner
#define THR 1e-12f            // relative skip threshold (cos^2)

// Scratch (device globals: allocation-free per harness rules)
__device__ float g_A[BB * HH * CW];     // masked, scaled input  [b][h][cw]
__device__ float g_G[BB * NN * NN];     // Gram A A^T per image
__device__ float g_Ut[BB * TAIL * NN];  // tail eigenvectors, row t = u_t^T
__device__ int   g_cnt[BB];             // observed-entry counts

// ---------------------------------------------------------------------------
// K1: A = (2x-1)*mask in [B,H,CW] layout; per-image mask count via atomics.
// ---------------------------------------------------------------------------
__global__ void build_kernel(const float* __restrict__ x,
                             const int* __restrict__ mask) {
    int idx = blockIdx.x * 256 + threadIdx.x;
    int b   = idx / (HH * CW);
    int rem = idx - b * (HH * CW);
    int h   = rem / CW;
    int cw  = rem - h * CW;
    int c   = cw / WW;
    int w   = cw - c * WW;

    int m = mask[idx];
    float xv = x[((b * CC + c) * HH + h) * WW + w];
    g_A[idx] = m ? (2.0f * xv - 1.0f) : 0.0f;

    int s = m;
    #pragma unroll
    for (int o = 16; o; o >>= 1) s += __shfl_xor_sync(0xffffffffu, s, o);
    __shared__ int ss[8];
    int warp = threadIdx.x >> 5, lane = threadIdx.x & 31;
    if (lane == 0) ss[warp] = s;
    __syncthreads();
    if (threadIdx.x == 0) {
        int t = 0;
        #pragma unroll
        for (int i = 0; i < 8; i++) t += ss[i];
        atomicAdd(&g_cnt[b], t);
    }
}

// ---------------------------------------------------------------------------
// K2: G = A A^T per image. grid (7,7,BB), block (16,16), 2x2 micro-tile.
// ---------------------------------------------------------------------------
__global__ void gram_kernel() {
    __shared__ float As[32][33];
    __shared__ float Bs[32][33];
    int b  = blockIdx.z;
    int i0 = blockIdx.y * 32, j0 = blockIdx.x * 32;
    const float* Ab = g_A + (size_t)b * HH * CW;
    int tx = threadIdx.x, ty = threadIdx.y;
    int t = ty * 16 + tx;

    float a00 = 0.f, a01 = 0.f, a10 = 0.f, a11 = 0.f;
    for (int k0 = 0; k0 < CW; k0 += 32) {
        #pragma unroll
        for (int q = 0; q < 4; q++) {
            int e = t + q * 256;
            int rr = e >> 5, kk = e & 31;
            As[rr][kk] = Ab[(i0 + rr) * CW + k0 + kk];
            Bs[rr][kk] = Ab[(j0 + rr) * CW + k0 + kk];
        }
        __syncthreads();
        #pragma unroll
        for (int kk = 0; kk < 32; kk++) {
            float x0 = As[2 * ty][kk], x1 = As[2 * ty + 1][kk];
            float y0 = Bs[2 * tx][kk], y1 = Bs[2 * tx + 1][kk];
            a00 += x0 * y0; a01 += x0 * y1;
            a10 += x1 * y0; a11 += x1 * y1;
        }
        __syncthreads();
    }
    float* Gb = g_G + (size_t)b * NN * NN;
    Gb[(i0 + 2 * ty    ) * NN + j0 + 2 * tx    ] = a00;
    Gb[(i0 + 2 * ty    ) * NN + j0 + 2 * tx + 1] = a01;
    Gb[(i0 + 2 * ty + 1) * NN + j0 + 2 * tx    ] = a10;
    Gb[(i0 + 2 * ty + 1) * NN + j0 + 2 * tx + 1] = a11;
}

// ---------------------------------------------------------------------------
// K3: one-sided Jacobi, 8-lane-group SIMD version.
// 896 threads = 28 warps = 112 groups of 8 lanes; group g handles pair g of
// the round. Columns accessed as 7 float4 per lane (conflict-free). Both
// columns held in registers across dot+rotate (no reload).
// Tournament: round r pairs (223, r) and ((r+p)%223, (r-p)%223).
// Incremental norms; relative skip threshold; early exit on clean sweep.
// ---------------------------------------------------------------------------
__device__ __forceinline__ void pair_ij(int r, int p, int& i, int& j) {
    if (p == 0) { i = NN - 1; j = r; }
    else {
        i = r + p; if (i >= NN - 1) i -= (NN - 1);
        j = r - p; if (j < 0)       j += (NN - 1);
    }
}

__global__ void __launch_bounds__(896, 1) jacobi_kernel() {
    extern __shared__ float sm[];
    float* W   = sm;                    // NN*NN, column-major
    float* nrm = sm + NN * NN;          // NN squared norms (maintained)
    int*   rnk = (int*)(nrm + NN);      // NN ranks
    __shared__ int rot_flag;

    int b = blockIdx.x;
    int tid = threadIdx.x, warp = tid >> 5, lane = tid & 31;
    int gl = lane & 7;                  // lane within 8-lane group
    int p  = (warp << 2) | (lane >> 3); // pair id 0..111
    const float* Gb = g_G + (size_t)b * NN * NN;

    for (int i = tid; i < NN * NN; i += 896) W[i] = Gb[i];
    __syncthreads();

    // initial column squared norms: 8 cols per warp, full-warp reduce
    #pragma unroll
    for (int k = 0; k < 8; k++) {
        int col = warp * 8 + k;
        const float* cc = W + col * NN;
        float s = 0.f;
        #pragma unroll
        for (int m = 0; m < 7; m++) { float v = cc[lane + 32 * m]; s += v * v; }
        #pragma unroll
        for (int o = 16; o; o >>= 1) s += __shfl_xor_sync(0xffffffffu, s, o);
        if (lane == 0) nrm[col] = s;
    }
    __syncthreads();

    for (int sw = 0; sw < NSWEEP; ++sw) {
        if (tid == 0) rot_flag = 0;
        __syncthreads();
        for (int r = 0; r < NN - 1; ++r) {
            int i, j; pair_ij(r, p, i, j);
            float4* ci = (float4*)(W + i * NN);
            float4* cj = (float4*)(W + j * NN);

            // dot over the group's 28-element slices; hold BOTH columns
            float4 wi[7], wj[7];
            float pp = 0.f;
            #pragma unroll
            for (int m = 0; m < 7; m++) {
                float4 a = ci[gl + 8 * m];
                float4 u = cj[gl + 8 * m];
                wi[m] = a; wj[m] = u;
                pp += a.x * u.x + a.y * u.y + a.z * u.z + a.w * u.w;
            }
            pp += __shfl_xor_sync(0xffffffffu, pp, 4);
            pp += __shfl_xor_sync(0xffffffffu, pp, 2);
            pp += __shfl_xor_sync(0xffffffffu, pp, 1);

            float qi = nrm[i], qj = nrm[j];
            if (pp * pp > THR * qi * qj) {     // uniform within group
                float tau = (qj - qi) / (2.0f * pp);
                float tt = 1.0f / (fabsf(tau) + sqrtf(1.0f + tau * tau));
                if (tau < 0.f) tt = -tt;
                float c = rsqrtf(1.0f + tt * tt);
                float s = c * tt;
                #pragma unroll
                for (int m = 0; m < 7; m++) {
                    float4 a = wi[m], u = wj[m];
                    float4 ni, nj;
                    ni.x = c * a.x - s * u.x;  nj.x = s * a.x + c * u.x;
                    ni.y = c * a.y - s * u.y;  nj.y = s * a.y + c * u.y;
                    ni.z = c * a.z - s * u.z;  nj.z = s * a.z + c * u.z;
                    ni.w = c * a.w - s * u.w;  nj.w = s * a.w + c * u.w;
                    ci[gl + 8 * m] = ni;
                    cj[gl + 8 * m] = nj;
                }
                if (gl == 0) {
                    float c2 = c * c, s2 = s * s, cs2 = 2.f * c * s;
                    nrm[i] = c2 * qi - cs2 * pp + s2 * qj;
                    nrm[j] = s2 * qi + cs2 * pp + c2 * qj;
                    rot_flag = 1;
                }
            }
            __syncthreads();
        }
        int done = (rot_flag == 0);
        __syncthreads();        // all reads of flag precede next reset
        if (done) break;
    }

    // rank of each column (0 = smallest norm), deterministic tie-break
    if (tid < NN) {
        float mine = nrm[tid];
        int rk = 0;
        for (int j = 0; j < NN; j++) {
            float o = nrm[j];
            rk += (o < mine) || (o == mine && j < tid);
        }
        rnk[tid] = rk;
    }
    __syncthreads();

    // write normalized tail-45 eigenvectors (rows of Ut^T), coalesced
    for (int t = 0; t < NN; t++) {
        int rk = rnk[t];
        if (rk < TAIL) {
            float inv = rsqrtf(nrm[t]);   // 1/lambda
            for (int rr = tid; rr < NN; rr += 896)
                g_Ut[((size_t)b * TAIL + rk) * NN + rr] = W[t * NN + rr] * inv;
        }
    }
}

// ---------------------------------------------------------------------------
// K4: R = A - Ut (Ut^T A); epilogue: /p_obs, clip, (r+1)/2, scatter to NCHW.
// Two CTAs per image (336 columns each), T in 45 registers/thread.
// ---------------------------------------------------------------------------
__global__ void __launch_bounds__(336, 2) recon_kernel(float* __restrict__ out) {
    __shared__ __align__(16) float sU[TAIL * NN];
    int b = blockIdx.x >> 1, half = blockIdx.x & 1;
    int tid = threadIdx.x;
    int cw  = half * 336 + tid;
    const float* Ub = g_Ut + (size_t)b * TAIL * NN;
    for (int i = tid; i < TAIL * NN; i += 336) sU[i] = Ub[i];
    __syncthreads();

    const float* Ab = g_A + (size_t)b * HH * CW;
    float inv_p = (float)(HH * CW) / (float)g_cnt[b];

    float acc[TAIL];
    #pragma unroll
    for (int t = 0; t < TAIL; t++) acc[t] = 0.f;

    for (int h = 0; h < HH; h += 4) {
        float a0 = Ab[(h + 0) * CW + cw];
        float a1 = Ab[(h + 1) * CW + cw];
        float a2 = Ab[(h + 2) * CW + cw];
        float a3 = Ab[(h + 3) * CW + cw];
        #pragma unroll
        for (int t = 0; t < TAIL; t++) {
            float4 u = *(const float4*)&sU[t * NN + h];
            acc[t] += u.x * a0 + u.y * a1 + u.z * a2 + u.w * a3;
        }
    }

    int c = cw / WW, w = cw - c * WW;
    float* ob = out + (((size_t)b * CC + c) * HH) * WW + w;

    for (int h = 0; h < HH; h += 4) {
        float a0 = Ab[(h + 0) * CW + cw];
        float a1 = Ab[(h + 1) * CW + cw];
        float a2 = Ab[(h + 2) * CW + cw];
        float a3 = Ab[(h + 3) * CW + cw];
        float s0 = 0.f, s1 = 0.f, s2 = 0.f, s3 = 0.f;
        #pragma unroll
        for (int t = 0; t < TAIL; t++) {
            float4 u = *(const float4*)&sU[t * NN + h];
            float tv = acc[t];
            s0 += u.x * tv; s1 += u.y * tv; s2 += u.z * tv; s3 += u.w * tv;
        }
        float r0 = (a0 - s0) * inv_p;
        float r1 = (a1 - s1) * inv_p;
        float r2 = (a2 - s2) * inv_p;
        float r3 = (a3 - s3) * inv_p;
        r0 = fminf(1.f, fmaxf(-1.f, r0));
        r1 = fminf(1.f, fmaxf(-1.f, r1));
        r2 = fminf(1.f, fmaxf(-1.f, r2));
        r3 = fminf(1.f, fmaxf(-1.f, r3));
        ob[(h + 0) * WW] = 0.5f * r0 + 0.5f;
        ob[(h + 1) * WW] = 0.5f * r1 + 0.5f;
        ob[(h + 2) * WW] = 0.5f * r2 + 0.5f;
        ob[(h + 3) * WW] = 0.5f * r3 + 0.5f;
    }
}

// ---------------------------------------------------------------------------
extern "C" void kernel_launch(void* const* d_in, const int* in_sizes, int n_in,
                              void* d_out, int out_size) {
    const float* x    = (const float*)d_in[0];
    const int*   mask = (const int*)d_in[1];
    float*       out  = (float*)d_out;

    const int JAC_SMEM = (NN * NN + NN) * (int)sizeof(float) + NN * (int)sizeof(int);

    void* cntp = nullptr;
    cudaGetSymbolAddress(&cntp, g_cnt);
    cudaMemsetAsync(cntp, 0, BB * sizeof(int));

    cudaFuncSetAttribute(jacobi_kernel,
                         cudaFuncAttributeMaxDynamicSharedMemorySize, JAC_SMEM);

    build_kernel<<<BB * HH * CW / 256, 256>>>(x, mask);
    gram_kernel<<<dim3(7, 7, BB), dim3(16, 16)>>>();
    jacobi_kernel<<<BB, 896, JAC_SMEM>>>();
    recon_kernel<<<2 * BB, 336>>>(out);
}

// round 13
// speedup vs baseline: 2.1952x; 1.0044x over previous
#include <cuda_runtime.h>
#include <cstdint>

// Problem constants (fixed shapes from setup_inputs)
#define BB 64
#define CC 3
#define HH 224
#define WW 224
#define CW (CC * WW)          // 672
#define NN 224                // Gram size
#define TAIL 45               // 224 - int(0.8*224)
#define NSWEEP 8              // cap; early-exit may trigger sooner
#define THR 1e-11f            // relative skip threshold (cos^2)

// Scratch (device globals: allocation-free per harness rules)
__device__ float g_A[BB * HH * CW];     // masked, scaled input  [b][h][cw]
__device__ float g_G[BB * NN * NN];     // Gram A A^T per image
__device__ float g_Ut[BB * TAIL * NN];  // tail eigenvectors, row t = u_t^T
__device__ int   g_cnt[BB];             // observed-entry counts

// ---------------------------------------------------------------------------
// K1: A = (2x-1)*mask in [B,H,CW] layout; per-image mask count via atomics.
// ---------------------------------------------------------------------------
__global__ void build_kernel(const float* __restrict__ x,
                             const int* __restrict__ mask) {
    int idx = blockIdx.x * 256 + threadIdx.x;
    int b   = idx / (HH * CW);
    int rem = idx - b * (HH * CW);
    int h   = rem / CW;
    int cw  = rem - h * CW;
    int c   = cw / WW;
    int w   = cw - c * WW;

    int m = mask[idx];
    float xv = x[((b * CC + c) * HH + h) * WW + w];
    g_A[idx] = m ? (2.0f * xv - 1.0f) : 0.0f;

    int s = m;
    #pragma unroll
    for (int o = 16; o; o >>= 1) s += __shfl_xor_sync(0xffffffffu, s, o);
    __shared__ int ss[8];
    int warp = threadIdx.x >> 5, lane = threadIdx.x & 31;
    if (lane == 0) ss[warp] = s;
    __syncthreads();
    if (threadIdx.x == 0) {
        int t = 0;
        #pragma unroll
        for (int i = 0; i < 8; i++) t += ss[i];
        atomicAdd(&g_cnt[b], t);
    }
}

// ---------------------------------------------------------------------------
// K2: G = A A^T per image. grid (7,7,BB), block (16,16), 2x2 micro-tile.
// ---------------------------------------------------------------------------
__global__ void gram_kernel() {
    __shared__ float As[32][33];
    __shared__ float Bs[32][33];
    int b  = blockIdx.z;
    int i0 = blockIdx.y * 32, j0 = blockIdx.x * 32;
    const float* Ab = g_A + (size_t)b * HH * CW;
    int tx = threadIdx.x, ty = threadIdx.y;
    int t = ty * 16 + tx;

    float a00 = 0.f, a01 = 0.f, a10 = 0.f, a11 = 0.f;
    for (int k0 = 0; k0 < CW; k0 += 32) {
        #pragma unroll
        for (int q = 0; q < 4; q++) {
            int e = t + q * 256;
            int rr = e >> 5, kk = e & 31;
            As[rr][kk] = Ab[(i0 + rr) * CW + k0 + kk];
            Bs[rr][kk] = Ab[(j0 + rr) * CW + k0 + kk];
        }
        __syncthreads();
        #pragma unroll
        for (int kk = 0; kk < 32; kk++) {
            float x0 = As[2 * ty][kk], x1 = As[2 * ty + 1][kk];
            float y0 = Bs[2 * tx][kk], y1 = Bs[2 * tx + 1][kk];
            a00 += x0 * y0; a01 += x0 * y1;
            a10 += x1 * y0; a11 += x1 * y1;
        }
        __syncthreads();
    }
    float* Gb = g_G + (size_t)b * NN * NN;
    Gb[(i0 + 2 * ty    ) * NN + j0 + 2 * tx    ] = a00;
    Gb[(i0 + 2 * ty    ) * NN + j0 + 2 * tx + 1] = a01;
    Gb[(i0 + 2 * ty + 1) * NN + j0 + 2 * tx    ] = a10;
    Gb[(i0 + 2 * ty + 1) * NN + j0 + 2 * tx + 1] = a11;
}

// ---------------------------------------------------------------------------
// K3: one-sided Jacobi, 8-lane-group SIMD version.
// 896 threads = 28 warps = 112 groups of 8 lanes; group g handles pair g of
// the round. Columns accessed as 7 float4 per lane (conflict-free). Both
// columns held in registers across dot+rotate (no reload).
// Tournament: round r pairs (223, r) and ((r+p)%223, (r-p)%223).
// Incremental norms; relative skip threshold; early exit on clean sweep.
// ---------------------------------------------------------------------------
__device__ __forceinline__ void pair_ij(int r, int p, int& i, int& j) {
    if (p == 0) { i = NN - 1; j = r; }
    else {
        i = r + p; if (i >= NN - 1) i -= (NN - 1);
        j = r - p; if (j < 0)       j += (NN - 1);
    }
}

__global__ void __launch_bounds__(896, 1) jacobi_kernel() {
    extern __shared__ float sm[];
    float* W   = sm;                    // NN*NN, column-major
    float* nrm = sm + NN * NN;          // NN squared norms (maintained)
    int*   rnk = (int*)(nrm + NN);      // NN ranks
    __shared__ int rot_flag;

    int b = blockIdx.x;
    int tid = threadIdx.x, warp = tid >> 5, lane = tid & 31;
    int gl = lane & 7;                  // lane within 8-lane group
    int p  = (warp << 2) | (lane >> 3); // pair id 0..111
    const float* Gb = g_G + (size_t)b * NN * NN;

    for (int i = tid; i < NN * NN; i += 896) W[i] = Gb[i];
    __syncthreads();

    // initial column squared norms: 8 cols per warp, full-warp reduce
    #pragma unroll
    for (int k = 0; k < 8; k++) {
        int col = warp * 8 + k;
        const float* cc = W + col * NN;
        float s = 0.f;
        #pragma unroll
        for (int m = 0; m < 7; m++) { float v = cc[lane + 32 * m]; s += v * v; }
        #pragma unroll
        for (int o = 16; o; o >>= 1) s += __shfl_xor_sync(0xffffffffu, s, o);
        if (lane == 0) nrm[col] = s;
    }
    __syncthreads();

    for (int sw = 0; sw < NSWEEP; ++sw) {
        if (tid == 0) rot_flag = 0;
        __syncthreads();
        for (int r = 0; r < NN - 1; ++r) {
            int i, j; pair_ij(r, p, i, j);
            float4* ci = (float4*)(W + i * NN);
            float4* cj = (float4*)(W + j * NN);

            // dot over the group's 28-element slices; hold BOTH columns
            float4 wi[7], wj[7];
            float pp = 0.f;
            #pragma unroll
            for (int m = 0; m < 7; m++) {
                float4 a = ci[gl + 8 * m];
                float4 u = cj[gl + 8 * m];
                wi[m] = a; wj[m] = u;
                pp += a.x * u.x + a.y * u.y + a.z * u.z + a.w * u.w;
            }
            pp += __shfl_xor_sync(0xffffffffu, pp, 4);
            pp += __shfl_xor_sync(0xffffffffu, pp, 2);
            pp += __shfl_xor_sync(0xffffffffu, pp, 1);

            float qi = nrm[i], qj = nrm[j];
            if (pp * pp > THR * qi * qj) {     // uniform within group
                float tau = (qj - qi) / (2.0f * pp);
                float tt = 1.0f / (fabsf(tau) + sqrtf(1.0f + tau * tau));
                if (tau < 0.f) tt = -tt;
                float c = rsqrtf(1.0f + tt * tt);
                float s = c * tt;
                #pragma unroll
                for (int m = 0; m < 7; m++) {
                    float4 a = wi[m], u = wj[m];
                    float4 ni, nj;
                    ni.x = c * a.x - s * u.x;  nj.x = s * a.x + c * u.x;
                    ni.y = c * a.y - s * u.y;  nj.y = s * a.y + c * u.y;
                    ni.z = c * a.z - s * u.z;  nj.z = s * a.z + c * u.z;
                    ni.w = c * a.w - s * u.w;  nj.w = s * a.w + c * u.w;
                    ci[gl + 8 * m] = ni;
                    cj[gl + 8 * m] = nj;
                }
                if (gl == 0) {
                    float c2 = c * c, s2 = s * s, cs2 = 2.f * c * s;
                    nrm[i] = c2 * qi - cs2 * pp + s2 * qj;
                    nrm[j] = s2 * qi + cs2 * pp + c2 * qj;
                    rot_flag = 1;
                }
            }
            __syncthreads();
        }
        int done = (rot_flag == 0);
        __syncthreads();        // all reads of flag precede next reset
        if (done) break;
    }

    // rank of each column (0 = smallest norm), deterministic tie-break
    if (tid < NN) {
        float mine = nrm[tid];
        int rk = 0;
        for (int j = 0; j < NN; j++) {
            float o = nrm[j];
            rk += (o < mine) || (o == mine && j < tid);
        }
        rnk[tid] = rk;
    }
    __syncthreads();

    // write normalized tail-45 eigenvectors (rows of Ut^T), coalesced
    for (int t = 0; t < NN; t++) {
        int rk = rnk[t];
        if (rk < TAIL) {
            float inv = rsqrtf(nrm[t]);   // 1/lambda
            for (int rr = tid; rr < NN; rr += 896)
                g_Ut[((size_t)b * TAIL + rk) * NN + rr] = W[t * NN + rr] * inv;
        }
    }
}

// ---------------------------------------------------------------------------
// K4: R = A - Ut (Ut^T A); epilogue: /p_obs, clip, (r+1)/2, scatter to NCHW.
// Two CTAs per image (336 columns each), T in 45 registers/thread.
// ---------------------------------------------------------------------------
__global__ void __launch_bounds__(336, 2) recon_kernel(float* __restrict__ out) {
    __shared__ __align__(16) float sU[TAIL * NN];
    int b = blockIdx.x >> 1, half = blockIdx.x & 1;
    int tid = threadIdx.x;
    int cw  = half * 336 + tid;
    const float* Ub = g_Ut + (size_t)b * TAIL * NN;
    for (int i = tid; i < TAIL * NN; i += 336) sU[i] = Ub[i];
    __syncthreads();

    const float* Ab = g_A + (size_t)b * HH * CW;
    float inv_p = (float)(HH * CW) / (float)g_cnt[b];

    float acc[TAIL];
    #pragma unroll
    for (int t = 0; t < TAIL; t++) acc[t] = 0.f;

    for (int h = 0; h < HH; h += 4) {
        float a0 = Ab[(h + 0) * CW + cw];
        float a1 = Ab[(h + 1) * CW + cw];
        float a2 = Ab[(h + 2) * CW + cw];
        float a3 = Ab[(h + 3) * CW + cw];
        #pragma unroll
        for (int t = 0; t < TAIL; t++) {
            float4 u = *(const float4*)&sU[t * NN + h];
            acc[t] += u.x * a0 + u.y * a1 + u.z * a2 + u.w * a3;
        }
    }

    int c = cw / WW, w = cw - c * WW;
    float* ob = out + (((size_t)b * CC + c) * HH) * WW + w;

    for (int h = 0; h < HH; h += 4) {
        float a0 = Ab[(h + 0) * CW + cw];
        float a1 = Ab[(h + 1) * CW + cw];
        float a2 = Ab[(h + 2) * CW + cw];
        float a3 = Ab[(h + 3) * CW + cw];
        float s0 = 0.f, s1 = 0.f, s2 = 0.f, s3 = 0.f;
        #pragma unroll
        for (int t = 0; t < TAIL; t++) {
            float4 u = *(const float4*)&sU[t * NN + h];
            float tv = acc[t];
            s0 += u.x * tv; s1 += u.y * tv; s2 += u.z * tv; s3 += u.w * tv;
        }
        float r0 = (a0 - s0) * inv_p;
        float r1 = (a1 - s1) * inv_p;
        float r2 = (a2 - s2) * inv_p;
        float r3 = (a3 - s3) * inv_p;
        r0 = fminf(1.f, fmaxf(-1.f, r0));
        r1 = fminf(1.f, fmaxf(-1.f, r1));
        r2 = fminf(1.f, fmaxf(-1.f, r2));
        r3 = fminf(1.f, fmaxf(-1.f, r3));
        ob[(h + 0) * WW] = 0.5f * r0 + 0.5f;
        ob[(h + 1) * WW] = 0.5f * r1 + 0.5f;
        ob[(h + 2) * WW] = 0.5f * r2 + 0.5f;
        ob[(h + 3) * WW] = 0.5f * r3 + 0.5f;
    }
}

// ---------------------------------------------------------------------------
extern "C" void kernel_launch(void* const* d_in, const int* in_sizes, int n_in,
                              void* d_out, int out_size) {
    const float* x    = (const float*)d_in[0];
    const int*   mask = (const int*)d_in[1];
    float*       out  = (float*)d_out;

    const int JAC_SMEM = (NN * NN + NN) * (int)sizeof(float) + NN * (int)sizeof(int);

    void* cntp = nullptr;
    cudaGetSymbolAddress(&cntp, g_cnt);
    cudaMemsetAsync(cntp, 0, BB * sizeof(int));

    cudaFuncSetAttribute(jacobi_kernel,
                         cudaFuncAttributeMaxDynamicSharedMemorySize, JAC_SMEM);

    build_kernel<<<BB * HH * CW / 256, 256>>>(x, mask);
    gram_kernel<<<dim3(7, 7, BB), dim3(16, 16)>>>();
    jacobi_kernel<<<BB, 896, JAC_SMEM>>>();
    recon_kernel<<<2 * BB, 336>>>(out);
}

// round 14
// speedup vs baseline: 2.2204x; 1.0115x over previous
#include <cuda_runtime.h>
#include <cstdint>

// Problem constants (fixed shapes from setup_inputs)
#define BB 64
#define CC 3
#define HH 224
#define WW 224
#define CW (CC * WW)          // 672
#define NN 224                // Gram size
#define TAIL 45               // 224 - int(0.8*224)
#define NSWEEP 8              // cap; early-exit may trigger sooner
#define THR 1e-9f             // relative skip threshold (cos^2); ~3e-5 rad

// Scratch (device globals: allocation-free per harness rules)
__device__ float g_A[BB * HH * CW];     // masked, scaled input  [b][h][cw]
__device__ float g_G[BB * NN * NN];     // Gram A A^T per image
__device__ float g_Ut[BB * TAIL * NN];  // tail eigenvectors, row t = u_t^T
__device__ int   g_cnt[BB];             // observed-entry counts

// ---------------------------------------------------------------------------
// K1: A = (2x-1)*mask in [B,H,CW] layout; per-image mask count via atomics.
// ---------------------------------------------------------------------------
__global__ void build_kernel(const float* __restrict__ x,
                             const int* __restrict__ mask) {
    int idx = blockIdx.x * 256 + threadIdx.x;
    int b   = idx / (HH * CW);
    int rem = idx - b * (HH * CW);
    int h   = rem / CW;
    int cw  = rem - h * CW;
    int c   = cw / WW;
    int w   = cw - c * WW;

    int m = mask[idx];
    float xv = x[((b * CC + c) * HH + h) * WW + w];
    g_A[idx] = m ? (2.0f * xv - 1.0f) : 0.0f;

    int s = m;
    #pragma unroll
    for (int o = 16; o; o >>= 1) s += __shfl_xor_sync(0xffffffffu, s, o);
    __shared__ int ss[8];
    int warp = threadIdx.x >> 5, lane = threadIdx.x & 31;
    if (lane == 0) ss[warp] = s;
    __syncthreads();
    if (threadIdx.x == 0) {
        int t = 0;
        #pragma unroll
        for (int i = 0; i < 8; i++) t += ss[i];
        atomicAdd(&g_cnt[b], t);
    }
}

// ---------------------------------------------------------------------------
// K2: G = A A^T per image. grid (7,7,BB), block (16,16), 2x2 micro-tile.
// ---------------------------------------------------------------------------
__global__ void gram_kernel() {
    __shared__ float As[32][33];
    __shared__ float Bs[32][33];
    int b  = blockIdx.z;
    int i0 = blockIdx.y * 32, j0 = blockIdx.x * 32;
    const float* Ab = g_A + (size_t)b * HH * CW;
    int tx = threadIdx.x, ty = threadIdx.y;
    int t = ty * 16 + tx;

    float a00 = 0.f, a01 = 0.f, a10 = 0.f, a11 = 0.f;
    for (int k0 = 0; k0 < CW; k0 += 32) {
        #pragma unroll
        for (int q = 0; q < 4; q++) {
            int e = t + q * 256;
            int rr = e >> 5, kk = e & 31;
            As[rr][kk] = Ab[(i0 + rr) * CW + k0 + kk];
            Bs[rr][kk] = Ab[(j0 + rr) * CW + k0 + kk];
        }
        __syncthreads();
        #pragma unroll
        for (int kk = 0; kk < 32; kk++) {
            float x0 = As[2 * ty][kk], x1 = As[2 * ty + 1][kk];
            float y0 = Bs[2 * tx][kk], y1 = Bs[2 * tx + 1][kk];
            a00 += x0 * y0; a01 += x0 * y1;
            a10 += x1 * y0; a11 += x1 * y1;
        }
        __syncthreads();
    }
    float* Gb = g_G + (size_t)b * NN * NN;
    Gb[(i0 + 2 * ty    ) * NN + j0 + 2 * tx    ] = a00;
    Gb[(i0 + 2 * ty    ) * NN + j0 + 2 * tx + 1] = a01;
    Gb[(i0 + 2 * ty + 1) * NN + j0 + 2 * tx    ] = a10;
    Gb[(i0 + 2 * ty + 1) * NN + j0 + 2 * tx + 1] = a11;
}

// ---------------------------------------------------------------------------
// K3: one-sided Jacobi, 8-lane-group SIMD version.
// 896 threads = 28 warps = 112 groups of 8 lanes; group g handles pair g of
// the round. Columns accessed as 7 float4 per lane (conflict-free). Both
// columns held in registers across dot+rotate (no reload).
// Tournament: round r pairs (223, r) and ((r+p)%223, (r-p)%223).
// Incremental norms; relative skip threshold; early exit on clean sweep.
// ---------------------------------------------------------------------------
__device__ __forceinline__ void pair_ij(int r, int p, int& i, int& j) {
    if (p == 0) { i = NN - 1; j = r; }
    else {
        i = r + p; if (i >= NN - 1) i -= (NN - 1);
        j = r - p; if (j < 0)       j += (NN - 1);
    }
}

__global__ void __launch_bounds__(896, 1) jacobi_kernel() {
    extern __shared__ float sm[];
    float* W   = sm;                    // NN*NN, column-major
    float* nrm = sm + NN * NN;          // NN squared norms (maintained)
    int*   rnk = (int*)(nrm + NN);      // NN ranks
    __shared__ int rot_flag;

    int b = blockIdx.x;
    int tid = threadIdx.x, warp = tid >> 5, lane = tid & 31;
    int gl = lane & 7;                  // lane within 8-lane group
    int p  = (warp << 2) | (lane >> 3); // pair id 0..111
    const float* Gb = g_G + (size_t)b * NN * NN;

    for (int i = tid; i < NN * NN; i += 896) W[i] = Gb[i];
    __syncthreads();

    // initial column squared norms: 8 cols per warp, full-warp reduce
    #pragma unroll
    for (int k = 0; k < 8; k++) {
        int col = warp * 8 + k;
        const float* cc = W + col * NN;
        float s = 0.f;
        #pragma unroll
        for (int m = 0; m < 7; m++) { float v = cc[lane + 32 * m]; s += v * v; }
        #pragma unroll
        for (int o = 16; o; o >>= 1) s += __shfl_xor_sync(0xffffffffu, s, o);
        if (lane == 0) nrm[col] = s;
    }
    __syncthreads();

    for (int sw = 0; sw < NSWEEP; ++sw) {
        if (tid == 0) rot_flag = 0;
        __syncthreads();
        for (int r = 0; r < NN - 1; ++r) {
            int i, j; pair_ij(r, p, i, j);
            float4* ci = (float4*)(W + i * NN);
            float4* cj = (float4*)(W + j * NN);

            // dot over the group's 28-element slices; hold BOTH columns
            float4 wi[7], wj[7];
            float pp = 0.f;
            #pragma unroll
            for (int m = 0; m < 7; m++) {
                float4 a = ci[gl + 8 * m];
                float4 u = cj[gl + 8 * m];
                wi[m] = a; wj[m] = u;
                pp += a.x * u.x + a.y * u.y + a.z * u.z + a.w * u.w;
            }
            pp += __shfl_xor_sync(0xffffffffu, pp, 4);
            pp += __shfl_xor_sync(0xffffffffu, pp, 2);
            pp += __shfl_xor_sync(0xffffffffu, pp, 1);

            float qi = nrm[i], qj = nrm[j];
            if (pp * pp > THR * qi * qj) {     // uniform within group
                float tau = (qj - qi) / (2.0f * pp);
                float tt = 1.0f / (fabsf(tau) + sqrtf(1.0f + tau * tau));
                if (tau < 0.f) tt = -tt;
                float c = rsqrtf(1.0f + tt * tt);
                float s = c * tt;
                #pragma unroll
                for (int m = 0; m < 7; m++) {
                    float4 a = wi[m], u = wj[m];
                    float4 ni, nj;
                    ni.x = c * a.x - s * u.x;  nj.x = s * a.x + c * u.x;
                    ni.y = c * a.y - s * u.y;  nj.y = s * a.y + c * u.y;
                    ni.z = c * a.z - s * u.z;  nj.z = s * a.z + c * u.z;
                    ni.w = c * a.w - s * u.w;  nj.w = s * a.w + c * u.w;
                    ci[gl + 8 * m] = ni;
                    cj[gl + 8 * m] = nj;
                }
                if (gl == 0) {
                    float c2 = c * c, s2 = s * s, cs2 = 2.f * c * s;
                    nrm[i] = c2 * qi - cs2 * pp + s2 * qj;
                    nrm[j] = s2 * qi + cs2 * pp + c2 * qj;
                    rot_flag = 1;
                }
            }
            __syncthreads();
        }
        int done = (rot_flag == 0);
        __syncthreads();        // all reads of flag precede next reset
        if (done) break;
    }

    // rank of each column (0 = smallest norm), deterministic tie-break
    if (tid < NN) {
        float mine = nrm[tid];
        int rk = 0;
        for (int j = 0; j < NN; j++) {
            float o = nrm[j];
            rk += (o < mine) || (o == mine && j < tid);
        }
        rnk[tid] = rk;
    }
    __syncthreads();

    // write normalized tail-45 eigenvectors (rows of Ut^T), coalesced
    for (int t = 0; t < NN; t++) {
        int rk = rnk[t];
        if (rk < TAIL) {
            float inv = rsqrtf(nrm[t]);   // 1/lambda
            for (int rr = tid; rr < NN; rr += 896)
                g_Ut[((size_t)b * TAIL + rk) * NN + rr] = W[t * NN + rr] * inv;
        }
    }
}

// ---------------------------------------------------------------------------
// K4: R = A - Ut (Ut^T A); epilogue: /p_obs, clip, (r+1)/2, scatter to NCHW.
// Two CTAs per image (336 columns each), T in 45 registers/thread.
// ---------------------------------------------------------------------------
__global__ void __launch_bounds__(336, 2) recon_kernel(float* __restrict__ out) {
    __shared__ __align__(16) float sU[TAIL * NN];
    int b = blockIdx.x >> 1, half = blockIdx.x & 1;
    int tid = threadIdx.x;
    int cw  = half * 336 + tid;
    const float* Ub = g_Ut + (size_t)b * TAIL * NN;
    for (int i = tid; i < TAIL * NN; i += 336) sU[i] = Ub[i];
    __syncthreads();

    const float* Ab = g_A + (size_t)b * HH * CW;
    float inv_p = (float)(HH * CW) / (float)g_cnt[b];

    float acc[TAIL];
    #pragma unroll
    for (int t = 0; t < TAIL; t++) acc[t] = 0.f;

    for (int h = 0; h < HH; h += 4) {
        float a0 = Ab[(h + 0) * CW + cw];
        float a1 = Ab[(h + 1) * CW + cw];
        float a2 = Ab[(h + 2) * CW + cw];
        float a3 = Ab[(h + 3) * CW + cw];
        #pragma unroll
        for (int t = 0; t < TAIL; t++) {
            float4 u = *(const float4*)&sU[t * NN + h];
            acc[t] += u.x * a0 + u.y * a1 + u.z * a2 + u.w * a3;
        }
    }

    int c = cw / WW, w = cw - c * WW;
    float* ob = out + (((size_t)b * CC + c) * HH) * WW + w;

    for (int h = 0; h < HH; h += 4) {
        float a0 = Ab[(h + 0) * CW + cw];
        float a1 = Ab[(h + 1) * CW + cw];
        float a2 = Ab[(h + 2) * CW + cw];
        float a3 = Ab[(h + 3) * CW + cw];
        float s0 = 0.f, s1 = 0.f, s2 = 0.f, s3 = 0.f;
        #pragma unroll
        for (int t = 0; t < TAIL; t++) {
            float4 u = *(const float4*)&sU[t * NN + h];
            float tv = acc[t];
            s0 += u.x * tv; s1 += u.y * tv; s2 += u.z * tv; s3 += u.w * tv;
        }
        float r0 = (a0 - s0) * inv_p;
        float r1 = (a1 - s1) * inv_p;
        float r2 = (a2 - s2) * inv_p;
        float r3 = (a3 - s3) * inv_p;
        r0 = fminf(1.f, fmaxf(-1.f, r0));
        r1 = fminf(1.f, fmaxf(-1.f, r1));
        r2 = fminf(1.f, fmaxf(-1.f, r2));
        r3 = fminf(1.f, fmaxf(-1.f, r3));
        ob[(h + 0) * WW] = 0.5f * r0 + 0.5f;
        ob[(h + 1) * WW] = 0.5f * r1 + 0.5f;
        ob[(h + 2) * WW] = 0.5f * r2 + 0.5f;
        ob[(h + 3) * WW] = 0.5f * r3 + 0.5f;
    }
}

// ---------------------------------------------------------------------------
extern "C" void kernel_launch(void* const* d_in, const int* in_sizes, int n_in,
                              void* d_out, int out_size) {
    const float* x    = (const float*)d_in[0];
    const int*   mask = (const int*)d_in[1];
    float*       out  = (float*)d_out;

    const int JAC_SMEM = (NN * NN + NN) * (int)sizeof(float) + NN * (int)sizeof(int);

    void* cntp = nullptr;
    cudaGetSymbolAddress(&cntp, g_cnt);
    cudaMemsetAsync(cntp, 0, BB * sizeof(int));

    cudaFuncSetAttribute(jacobi_kernel,
                         cudaFuncAttributeMaxDynamicSharedMemorySize, JAC_SMEM);

    build_kernel<<<BB * HH * CW / 256, 256>>>(x, mask);
    gram_kernel<<<dim3(7, 7, BB), dim3(16, 16)>>>();
    jacobi_kernel<<<BB, 896, JAC_SMEM>>>();
    recon_kernel<<<2 * BB, 336>>>(out);
}